// round 11
// baseline (speedup 1.0000x reference)
#include <cuda_runtime.h>
#include <cuda_bf16.h>
#include <math.h>
#include <stdint.h>

// Problem constants
#define Nn 2
#define Tt 2048
#define DMc 1024
#define Hh 8
#define Ee 4
#define Ll 32
#define DKc 64
#define DVc 64
#define NT (Nn*Tt)           // 4096 tokens
#define REC_T (Tt+Ll)        // 2080 rec positions per (n,e)
#define M_CH (Tt/Ll)         // 64 chunks

typedef __nv_bfloat16 bf16;
typedef __nv_bfloat162 bf162;

// Scratch (allocation-free rule: __device__ globals)
__device__ float d_K[NT*Hh*DKc];       // split-K half 0
__device__ float d_K2[NT*Hh*DKc];      // split-K half 1
__device__ float d_V[NT*Hh*DVc];
__device__ float d_V2[NT*Hh*DVc];
__device__ float d_Q[NT*Hh*DKc];
__device__ float d_Q2[NT*Hh*DKc];
__device__ float d_Gsig[NT*Hh*Ee];     // (token, h*4+e) POST-sigmoid
__device__ float d_A[Nn*Ee*Tt];        // (n,e,t)
__device__ float d_gK[Nn*Ee*Tt*DKc];   // (n,e,t,d)
__device__ float d_gV[Nn*Ee*Tt*DVc];
__device__ float d_recK[Nn*Ee*REC_T*DKc]; // (n,e,pos,d), pos 0..L-1 = init
__device__ float d_recV[Nn*Ee*REC_T*DVc];

// Pre-split bf16 hi/lo planes
__device__ bf16 d_Xh[NT*DMc],    d_Xl[NT*DMc];
__device__ bf16 d_wKh[512*1024], d_wKl[512*1024];
__device__ bf16 d_wVh[512*1024], d_wVl[512*1024];
__device__ bf16 d_wQh[512*1024], d_wQl[512*1024];
__device__ bf16 d_wOh[1024*512], d_wOl[1024*512];   // wO transposed + split
__device__ bf16 d_Yh[NT*Hh*DVc], d_Yl[NT*Hh*DVc];

// ---------------------------------------------------------------------------
// helpers
// ---------------------------------------------------------------------------
__device__ __forceinline__ uint32_t smem_u32(const void* p) {
    uint32_t a;
    asm("{ .reg .u64 t; cvta.to.shared.u64 t, %1; cvt.u32.u64 %0, t; }"
        : "=r"(a) : "l"(p));
    return a;
}

__device__ __forceinline__ void split_bf(float x, bf16& h, bf16& l) {
    h = __float2bfloat16(x);
    l = __float2bfloat16(x - __bfloat162float(h));
}

__device__ __forceinline__ void mma_bf16(float* c, const uint32_t* a, const uint32_t* b) {
    asm volatile("mma.sync.aligned.m16n8k16.row.col.f32.bf16.bf16.f32 "
        "{%0,%1,%2,%3}, {%4,%5,%6,%7}, {%8,%9}, {%0,%1,%2,%3};"
        : "+f"(c[0]), "+f"(c[1]), "+f"(c[2]), "+f"(c[3])
        : "r"(a[0]), "r"(a[1]), "r"(a[2]), "r"(a[3]), "r"(b[0]), "r"(b[1]));
}

__device__ __forceinline__ void ldsm4(uint32_t* r, uint32_t addr) {
    asm volatile("ldmatrix.sync.aligned.m8n8.x4.shared.b16 {%0,%1,%2,%3}, [%4];"
        : "=r"(r[0]), "=r"(r[1]), "=r"(r[2]), "=r"(r[3]) : "r"(addr));
}

__device__ __forceinline__ void cp16(uint32_t dst, const void* src) {
    asm volatile("cp.async.cg.shared.global [%0], [%1], 16;" :: "r"(dst), "l"(src));
}
#define CP_COMMIT() asm volatile("cp.async.commit_group;" ::: "memory")
#define CP_WAIT2()  asm volatile("cp.async.wait_group 2;" ::: "memory")

// ---------------------------------------------------------------------------
// 3x-split bf16 GEMM (m16n8k16 + ldmatrix): C[128x128] tile.
//  A planes: [*, Kstride] bf16 row-major; B planes likewise (C = A * B^T).
//  fp32 accumulate; acc = AhBh + AhBl + AlBh. Klen <= Kstride processed.
// 256 threads, warp tile 64x32. smem: 4-stage ring; per stage 4 planes of
// 128 rows x 12 uint32 (8 data kpairs + 4 pad -> LDSM-phase conflict-free).
// ---------------------------------------------------------------------------
#define SROW 12                        // uint32 per row
#define PLU (128*SROW)                 // uint32 per plane = 1536
#define STGU (4*PLU)                   // uint32 per stage = 6144 (24KB)
#define GSMB (4*STGU*4)                // bytes = 98304 (4 stages)

__device__ __forceinline__ void gemm3_tile(const bf16* __restrict__ Ah,
                                           const bf16* __restrict__ Al,
                                           const bf16* __restrict__ Bh,
                                           const bf16* __restrict__ Bl,
                                           float* __restrict__ C,
                                           int Ncol, int Kstride, int Klen) {
    extern __shared__ uint32_t smu[];
    const uint32_t sbase = smem_u32(smu);
    const int tid = threadIdx.x;
    const int warp = tid >> 5, lane = tid & 31;
    const int wm = (warp >> 2) * 64;      // 0 / 64
    const int wn = (warp & 3) * 32;       // 0..96
    const int r = lane >> 2, cf = lane & 3;

    const int row = tid >> 1, half = tid & 1;   // loader: 1 seg/plane/thread

    auto copy = [&](int kt, int slot) {
        uint32_t db = sbase + (uint32_t)(slot * STGU + row * SROW + half * 4) * 4u;
        size_t go = (size_t)row * Kstride + (size_t)kt * 16 + half * 8;
        cp16(db,                 Ah + go);
        cp16(db + PLU * 4u,      Al + go);
        cp16(db + 2u * PLU * 4u, Bh + go);
        cp16(db + 3u * PLU * 4u, Bl + go);
    };

    // ldmatrix lane-address components
    const uint32_t a_row = (uint32_t)(wm + ((lane >> 3) & 1) * 8 + (lane & 7));
    const uint32_t a_kof = (uint32_t)((lane >> 4) * 4);
    const uint32_t b_row = (uint32_t)(wn + ((lane >> 4) & 1) * 8 + (lane & 7));
    const uint32_t b_kof = (uint32_t)(((lane >> 3) & 1) * 4);

    float acc[4][4][4] = {};

    auto compute = [&](int slot) {
        const uint32_t S = sbase + (uint32_t)(slot * STGU) * 4u;
        uint32_t bh[2][4], bl[2][4];      // [nt-pair][4 regs]
        #pragma unroll
        for (int p = 0; p < 2; p++) {
            uint32_t ad = S + 2u * PLU * 4u + ((b_row + p * 16) * SROW + b_kof) * 4u;
            ldsm4(bh[p], ad);
            ldsm4(bl[p], ad + PLU * 4u);
        }
        #pragma unroll
        for (int mt = 0; mt < 4; mt++) {
            uint32_t ah[4], al[4];
            uint32_t ad = S + ((a_row + mt * 16) * SROW + a_kof) * 4u;
            ldsm4(ah, ad);
            ldsm4(al, ad + PLU * 4u);
            #pragma unroll
            for (int nt = 0; nt < 4; nt++) {
                const uint32_t* bhp = &bh[nt >> 1][(nt & 1) * 2];
                const uint32_t* blp = &bl[nt >> 1][(nt & 1) * 2];
                mma_bf16(acc[mt][nt], ah, bhp);
                mma_bf16(acc[mt][nt], ah, blp);
                mma_bf16(acc[mt][nt], al, bhp);
            }
        }
    };

    const int NK = Klen / 16;
    copy(0, 0); CP_COMMIT();
    copy(1, 1); CP_COMMIT();
    copy(2, 2); CP_COMMIT();
    for (int kt = 0; kt < NK; kt++) {
        CP_WAIT2();                       // stage kt arrived (3 commits back)
        __syncthreads();
        if (kt + 3 < NK) copy(kt + 3, (kt + 3) & 3);
        CP_COMMIT();                      // uniform commit (possibly empty)
        compute(kt & 3);
    }

    // Epilogue: mma C-fragment layout, float2 stores
    #pragma unroll
    for (int mt = 0; mt < 4; mt++) {
        int rowc = wm + mt * 16 + r;
        #pragma unroll
        for (int nt = 0; nt < 4; nt++) {
            int col = wn + nt * 8 + cf * 2;
            float2 lo = {acc[mt][nt][0], acc[mt][nt][1]};
            float2 hi = {acc[mt][nt][2], acc[mt][nt][3]};
            *(float2*)(C + (size_t)rowc * Ncol + col) = lo;
            *(float2*)(C + (size_t)(rowc + 8) * Ncol + col) = hi;
        }
    }
}

// K/V/Q projections, split-K x2, fused via blockIdx.z = proj*2 + khalf
__global__ void __launch_bounds__(256, 2) gemm_kvq() {
    const int proj = blockIdx.z >> 1;
    const int kh = blockIdx.z & 1;
    const bf16 *Bh, *Bl;
    float* C;
    if (proj == 0)      { Bh = d_wKh; Bl = d_wKl; C = kh ? d_K2 : d_K; }
    else if (proj == 1) { Bh = d_wVh; Bl = d_wVl; C = kh ? d_V2 : d_V; }
    else                { Bh = d_wQh; Bl = d_wQl; C = kh ? d_Q2 : d_Q; }
    const size_t ko = (size_t)kh * 512;
    gemm3_tile(d_Xh + (size_t)blockIdx.y * 128 * 1024 + ko,
               d_Xl + (size_t)blockIdx.y * 128 * 1024 + ko,
               Bh + (size_t)blockIdx.x * 128 * 1024 + ko,
               Bl + (size_t)blockIdx.x * 128 * 1024 + ko,
               C + (size_t)blockIdx.y * 128 * 512 + blockIdx.x * 128,
               512, 1024, 512);
}

// Output GEMM: out = Y * wO = Y * (wOT)^T
__global__ void __launch_bounds__(256, 2) gemm_out(float* __restrict__ out) {
    gemm3_tile(d_Yh + (size_t)blockIdx.y * 128 * 512, d_Yl + (size_t)blockIdx.y * 128 * 512,
               d_wOh + (size_t)blockIdx.x * 128 * 512, d_wOl + (size_t)blockIdx.x * 128 * 512,
               out + (size_t)blockIdx.y * 128 * 1024 + blockIdx.x * 128,
               1024, 512, 512);
}

// ---------------------------------------------------------------------------
// One-shot weight split: wK/wV/wQ -> bf16 hi/lo planes (by blockIdx.y)
// ---------------------------------------------------------------------------
__global__ void __launch_bounds__(256) split_w(const float* __restrict__ wK,
                                               const float* __restrict__ wV,
                                               const float* __restrict__ wQ) {
    const float* src = (blockIdx.y == 0) ? wK : (blockIdx.y == 1) ? wV : wQ;
    bf16* dh = (blockIdx.y == 0) ? d_wKh : (blockIdx.y == 1) ? d_wVh : d_wQh;
    bf16* dl = (blockIdx.y == 0) ? d_wKl : (blockIdx.y == 1) ? d_wVl : d_wQl;
    int i = blockIdx.x * 256 + threadIdx.x;      // float4 index, 131072 total
    float4 v = *(const float4*)(src + (size_t)i * 4);
    bf16 h[4], l[4];
    split_bf(v.x, h[0], l[0]); split_bf(v.y, h[1], l[1]);
    split_bf(v.z, h[2], l[2]); split_bf(v.w, h[3], l[3]);
    *(bf162*)(dh + (size_t)i * 4)     = bf162{h[0], h[1]};
    *(bf162*)(dh + (size_t)i * 4 + 2) = bf162{h[2], h[3]};
    *(bf162*)(dl + (size_t)i * 4)     = bf162{l[0], l[1]};
    *(bf162*)(dl + (size_t)i * 4 + 2) = bf162{l[2], l[3]};
}

// wO (512 x 1024 row-major) -> transposed + split (1024 x 512) bf16 hi/lo
__global__ void transpose_wo(const float* __restrict__ wo) {
    __shared__ float t[32][33];
    int bx = blockIdx.x * 32;   // over N (1024)
    int by = blockIdx.y * 32;   // over K (512)
    int x = threadIdx.x, y = threadIdx.y;
    #pragma unroll
    for (int j = 0; j < 32; j += 8)
        t[y + j][x] = wo[(size_t)(by + y + j) * 1024 + bx + x];
    __syncthreads();
    #pragma unroll
    for (int j = 0; j < 32; j += 8) {
        float v = t[x][y + j];
        bf16 h, l;
        split_bf(v, h, l);
        d_wOh[(size_t)(bx + y + j) * 512 + by + x] = h;
        d_wOl[(size_t)(bx + y + j) * 512 + by + x] = l;
    }
}

// ---------------------------------------------------------------------------
// G projection + bias + sigmoid; also emits X hi/lo bf16 planes.
// ---------------------------------------------------------------------------
__global__ void __launch_bounds__(256) g_kernel(const float* __restrict__ X,
                                                const float* __restrict__ wG,
                                                const float* __restrict__ bG) {
    __shared__ float xs[8][1024];
    const int tid = threadIdx.x;
    const int token0 = blockIdx.x * 8;
    #pragma unroll
    for (int i = 0; i < 8; i++) {
        int idx = tid + i * 256;              // float4 index 0..2047
        int tok = idx >> 8, c4 = idx & 255;
        float4 v = *(const float4*)(X + (size_t)(token0 + tok) * DMc + c4 * 4);
        *(float4*)&xs[tok][c4 * 4] = v;
        bf16 h[4], l[4];
        split_bf(v.x, h[0], l[0]); split_bf(v.y, h[1], l[1]);
        split_bf(v.z, h[2], l[2]); split_bf(v.w, h[3], l[3]);
        size_t o = (size_t)(token0 + tok) * DMc + c4 * 4;
        *(bf162*)(d_Xh + o)     = bf162{h[0], h[1]};
        *(bf162*)(d_Xh + o + 2) = bf162{h[2], h[3]};
        *(bf162*)(d_Xl + o)     = bf162{l[0], l[1]};
        *(bf162*)(d_Xl + o + 2) = bf162{l[2], l[3]};
    }
    __syncthreads();

    const int w = tid >> 5, lane = tid & 31;
    float acc[4][8] = {};
    #pragma unroll 4
    for (int j = 0; j < 32; j++) {
        int k = j * 32 + lane;
        float wv[4];
        #pragma unroll
        for (int o = 0; o < 4; o++)
            wv[o] = wG[(size_t)(w * 4 + o) * DMc + k];
        #pragma unroll
        for (int tok = 0; tok < 8; tok++) {
            float xv = xs[tok][k];
            #pragma unroll
            for (int o = 0; o < 4; o++)
                acc[o][tok] += wv[o] * xv;
        }
    }
    #pragma unroll
    for (int o = 0; o < 4; o++) {
        float bias = bG[w * 4 + o];
        #pragma unroll
        for (int tok = 0; tok < 8; tok++) {
            float v = acc[o][tok];
            #pragma unroll
            for (int off = 16; off; off >>= 1)
                v += __shfl_xor_sync(0xffffffffu, v, off);
            if (lane == 0)
                d_Gsig[(size_t)(token0 + tok) * (Hh * Ee) + w * 4 + o] =
                    1.f / (1.f + expf(-(v + bias)));
        }
    }
}

// ---------------------------------------------------------------------------
// Gating: per (n,e,t) compute gated_K, gated_V (sum over heads), and A.
// Sums the two split-K halves of K/V.
// ---------------------------------------------------------------------------
__global__ void __launch_bounds__(128) gated_kernel() {
    const int blk = blockIdx.x;
    const int t = blk % Tt;
    const int e = (blk / Tt) % Ee;
    const int n = blk / (Tt * Ee);
    const int token = n * Tt + t;
    __shared__ float g[Hh];
    const int tid = threadIdx.x;
    if (tid < Hh)
        g[tid] = d_Gsig[token * (Hh * Ee) + tid * Ee + e];
    __syncthreads();
    if (tid < 64) {
        float s = 0.f;
        #pragma unroll
        for (int h = 0; h < Hh; h++) {
            int idx = token * (Hh * DKc) + h * DKc + tid;
            s += g[h] * (d_K[idx] + d_K2[idx]);
        }
        d_gK[((n * Ee + e) * Tt + t) * DKc + tid] = s;
    } else {
        int dd = tid - 64;
        float s = 0.f;
        #pragma unroll
        for (int h = 0; h < Hh; h++) {
            int idx = token * (Hh * DVc) + h * DVc + dd;
            s += g[h] * (d_V[idx] + d_V2[idx]);
        }
        d_gV[((n * Ee + e) * Tt + t) * DVc + dd] = s;
    }
    if (tid == 0) {
        float sa = 0.f;
        #pragma unroll
        for (int h = 0; h < Hh; h++) sa += g[h];
        d_A[(n * Ee + e) * Tt + t] = 1.f - sa;
    }
}

// ---------------------------------------------------------------------------
// Scan: L-strided recurrence rec[t] = A[t]*rec[t-L] + gated[t].
// ---------------------------------------------------------------------------
__global__ void __launch_bounds__(128) scan_kernel(const float* __restrict__ initK,
                                                   const float* __restrict__ initV) {
    const int b = blockIdx.x;             // Nn*Ee*Ll = 256 blocks
    const int l = b % Ll;
    const int e = (b / Ll) % Ee;
    const int n = b / (Ll * Ee);
    const int d = threadIdx.x;
    const bool isK = d < 64;
    const int dd = isK ? d : d - 64;
    const float* init = isK ? initK : initV;
    const float* gsrc = isK ? d_gK : d_gV;
    float* rec = isK ? d_recK : d_recV;
    const int ne = n * Ee + e;
    float y = init[(e * Ll + l) * 64 + dd];
    rec[(ne * REC_T + l) * 64 + dd] = y;
    const float* Arow = d_A + ne * Tt;
    const float* grow = gsrc + ne * Tt * 64;
    float* rrow = rec + (ne * REC_T + Ll) * 64;
    #pragma unroll 4
    for (int m = 0; m < M_CH; m++) {
        int t = m * Ll + l;
        y = Arow[t] * y + grow[t * 64 + dd];
        rrow[t * 64 + dd] = y;
    }
}

// ---------------------------------------------------------------------------
// Attention: one block per 4 tokens (same n). All H=8 heads + 4 tokens share
// a 140-row window (E=4 experts x 35 positions). 512 threads, 2 CTAs/SM.
// Token tt slot j: e=j>>5, window row e*35 + tt + (j&31), pos = t0+1+tt+(j&31).
// Epilogue writes Y as bf16 hi/lo planes for the output GEMM.
// ---------------------------------------------------------------------------
#define TB 4
#define WR (Ee*(Ll+TB-1))              // 140 window rows
#define ATT_SMEM ((TB*512 + 2*WR*65 + TB*8*128) * 4)

__global__ void __launch_bounds__(512) attn_kernel() {
    extern __shared__ float smem[];
    float* qs = smem;                      // TB*512
    float* Ks = qs + TB * 512;             // WR*65 (padded rows)
    float* Vs = Ks + WR * 65;              // WR*65
    float* sc = Vs + WR * 65;              // TB*8*128
    const int token0 = blockIdx.x * TB;
    const int n = token0 / Tt, t0 = token0 % Tt;
    const int tid = threadIdx.x;

    #pragma unroll
    for (int i = 0; i < TB; i++) {
        int idx = tid + i * 512;           // 0..2047
        qs[idx] = d_Q[token0 * 512 + idx] + d_Q2[token0 * 512 + idx];
    }

    for (int i = tid; i < WR * 64; i += 512) {
        int j = i >> 6, dd = i & 63;
        int e = j / (Ll + TB - 1);
        int ii = j - e * (Ll + TB - 1);
        int pos = t0 + ii + 1;                      // <= 2079 < REC_T
        int off = ((n * Ee + e) * REC_T + pos) * 64 + dd;
        Ks[j * 65 + dd] = d_recK[off];
        Vs[j * 65 + dd] = d_recV[off];
    }
    __syncthreads();

    // scores: TB tokens x 8 heads x 128 slots = 4096 tasks
    #pragma unroll
    for (int r = 0; r < 8; r++) {
        int task = tid + r * 512;
        int tt = task >> 10;
        int h = (task >> 7) & 7;
        int j = task & 127;
        int e = j >> 5, l = j & 31;
        const float* qrow = qs + tt * 512 + h * 64;
        const float* krow = Ks + (e * (Ll + TB - 1) + tt + l) * 65;
        float s = 0.f;
        #pragma unroll
        for (int d = 0; d < 64; d++) s += qrow[d] * krow[d];
        sc[(tt * 8 + h) * 128 + j] = s * 0.125f;    // 1/sqrt(64)
    }
    __syncthreads();

    // softmax over 128 slots: 16 warps, each handles 2 (tt,h) pairs
    {
        int w = tid >> 5, lane = tid & 31;
        #pragma unroll
        for (int p = 0; p < 2; p++) {
            int pair = w * 2 + p;                   // 0..31
            float* row = sc + pair * 128;
            float v0 = row[lane], v1 = row[lane + 32];
            float v2 = row[lane + 64], v3 = row[lane + 96];
            float mx = fmaxf(fmaxf(v0, v1), fmaxf(v2, v3));
            #pragma unroll
            for (int o = 16; o; o >>= 1) mx = fmaxf(mx, __shfl_xor_sync(0xffffffffu, mx, o));
            float e0 = expf(v0 - mx), e1 = expf(v1 - mx);
            float e2 = expf(v2 - mx), e3 = expf(v3 - mx);
            float ssum = e0 + e1 + e2 + e3;
            #pragma unroll
            for (int o = 16; o; o >>= 1) ssum += __shfl_xor_sync(0xffffffffu, ssum, o);
            float inv = 1.f / ssum;
            row[lane]      = e0 * inv;
            row[lane + 32] = e1 * inv;
            row[lane + 64] = e2 * inv;
            row[lane + 96] = e3 * inv;
        }
    }
    __syncthreads();

    // output: TB x 8 heads x 64 dims = 2048 outputs, split to bf16 hi/lo
    #pragma unroll
    for (int r = 0; r < TB; r++) {
        int o = tid + r * 512;
        int tt = o >> 9;
        int rem = o & 511;
        int h = rem >> 6, dd = rem & 63;
        const float* arow = sc + (tt * 8 + h) * 128;
        float acc = 0.f;
        #pragma unroll 4
        for (int j = 0; j < 128; j++) {
            int e = j >> 5, l = j & 31;
            acc += arow[j] * Vs[(e * (Ll + TB - 1) + tt + l) * 65 + dd];
        }
        bf16 hp, lp;
        split_bf(acc, hp, lp);
        d_Yh[(token0 + tt) * 512 + rem] = hp;
        d_Yl[(token0 + tt) * 512 + rem] = lp;
    }
}

// ---------------------------------------------------------------------------
extern "C" void kernel_launch(void* const* d_in, const int* in_sizes, int n_in,
                              void* d_out, int out_size) {
    const float* X  = (const float*)d_in[0];
    const float* wG = (const float*)d_in[1];
    const float* bG = (const float*)d_in[2];
    const float* wK = (const float*)d_in[3];
    const float* wV = (const float*)d_in[4];
    const float* wQ = (const float*)d_in[5];
    const float* wO = (const float*)d_in[6];
    const float* iK = (const float*)d_in[7];
    const float* iV = (const float*)d_in[8];
    float* out = (float*)d_out;

    cudaFuncSetAttribute(gemm_kvq, cudaFuncAttributeMaxDynamicSharedMemorySize, GSMB);
    cudaFuncSetAttribute(gemm_out, cudaFuncAttributeMaxDynamicSharedMemorySize, GSMB);
    cudaFuncSetAttribute(attn_kernel, cudaFuncAttributeMaxDynamicSharedMemorySize, ATT_SMEM);

    // One-shot operand preparation (splits + transpose)
    split_w<<<dim3(512, 3), 256>>>(wK, wV, wQ);
    transpose_wo<<<dim3(32, 16), dim3(32, 8)>>>(wO);
    g_kernel<<<NT / 8, 256>>>(X, wG, bG);     // also emits d_Xh / d_Xl

    // K/V/Q projections, split-K x2: grid.z = proj*2 + khalf (768 CTAs)
    gemm_kvq<<<dim3(4, 32, 6), 256, GSMB>>>();

    gated_kernel<<<Nn * Ee * Tt, 128>>>();
    scan_kernel<<<Nn * Ee * Ll, 128>>>(iK, iV);

    attn_kernel<<<NT / TB, 512, ATT_SMEM>>>();

    // Output: out = Y * wO = Y * (wOT)^T
    gemm_out<<<dim3(8, 32), 256, GSMB>>>(out);
}

// round 12
// speedup vs baseline: 1.1423x; 1.1423x over previous
#include <cuda_runtime.h>
#include <cuda_bf16.h>
#include <math.h>
#include <stdint.h>

// Problem constants
#define Nn 2
#define Tt 2048
#define DMc 1024
#define Hh 8
#define Ee 4
#define Ll 32
#define DKc 64
#define DVc 64
#define NT (Nn*Tt)           // 4096 tokens
#define REC_T (Tt+Ll)        // 2080 rec positions per (n,e)
#define M_CH (Tt/Ll)         // 64 chunks

typedef __nv_bfloat16 bf16;
typedef __nv_bfloat162 bf162;

// Scratch (allocation-free rule: __device__ globals)
__device__ float d_K[NT*Hh*DKc];       // (token, h*64+d)
__device__ float d_V[NT*Hh*DVc];
__device__ float d_Q[NT*Hh*DKc];
__device__ float d_Gsig[NT*Hh*Ee];     // (token, h*4+e) POST-sigmoid
__device__ float d_A[Nn*Ee*Tt];        // (n,e,t)
__device__ float d_gK[Nn*Ee*Tt*DKc];   // (n,e,t,d)
__device__ float d_gV[Nn*Ee*Tt*DVc];
__device__ float d_recK[Nn*Ee*REC_T*DKc]; // (n,e,pos,d), pos 0..L-1 = init
__device__ float d_recV[Nn*Ee*REC_T*DVc];

// Pre-split bf16 hi/lo planes
__device__ bf16 d_Xh[NT*DMc],    d_Xl[NT*DMc];
__device__ bf16 d_wKh[512*1024], d_wKl[512*1024];
__device__ bf16 d_wVh[512*1024], d_wVl[512*1024];
__device__ bf16 d_wQh[512*1024], d_wQl[512*1024];
__device__ bf16 d_wOh[1024*512], d_wOl[1024*512];   // wO transposed + split
__device__ bf16 d_Yh[NT*Hh*DVc], d_Yl[NT*Hh*DVc];

// ---------------------------------------------------------------------------
// helpers
// ---------------------------------------------------------------------------
__device__ __forceinline__ uint32_t smem_u32(const void* p) {
    uint32_t a;
    asm("{ .reg .u64 t; cvta.to.shared.u64 t, %1; cvt.u32.u64 %0, t; }"
        : "=r"(a) : "l"(p));
    return a;
}

__device__ __forceinline__ void split_bf(float x, bf16& h, bf16& l) {
    h = __float2bfloat16(x);
    l = __float2bfloat16(x - __bfloat162float(h));
}

__device__ __forceinline__ void mma_bf16(float* c, const uint32_t* a, const uint32_t* b) {
    asm volatile("mma.sync.aligned.m16n8k16.row.col.f32.bf16.bf16.f32 "
        "{%0,%1,%2,%3}, {%4,%5,%6,%7}, {%8,%9}, {%0,%1,%2,%3};"
        : "+f"(c[0]), "+f"(c[1]), "+f"(c[2]), "+f"(c[3])
        : "r"(a[0]), "r"(a[1]), "r"(a[2]), "r"(a[3]), "r"(b[0]), "r"(b[1]));
}

__device__ __forceinline__ void ldsm4(uint32_t* r, uint32_t addr) {
    asm volatile("ldmatrix.sync.aligned.m8n8.x4.shared.b16 {%0,%1,%2,%3}, [%4];"
        : "=r"(r[0]), "=r"(r[1]), "=r"(r[2]), "=r"(r[3]) : "r"(addr));
}

__device__ __forceinline__ void cp16(uint32_t dst, const void* src) {
    asm volatile("cp.async.cg.shared.global [%0], [%1], 16;" :: "r"(dst), "l"(src));
}
#define CP_COMMIT() asm volatile("cp.async.commit_group;" ::: "memory")
#define CP_WAIT2()  asm volatile("cp.async.wait_group 2;" ::: "memory")

// ---------------------------------------------------------------------------
// 3x-split bf16 GEMM (m16n8k16 + ldmatrix): C[128x128] tile.
//  A planes: [Mtot, K] bf16 row-major; B planes: [Ntot, K] bf16 row-major
//  (C = A * B^T, fp32 accumulate; acc = AhBh + AhBl + AlBh).
// 256 threads, warp tile 64x32. smem: 4-stage ring; per stage 4 planes of
// 128 rows x 12 uint32 (8 data kpairs + 4 pad -> LDSM-phase conflict-free).
// Inner mma order groups by term (hh, hl, lh) so same-accumulator mmas are
// 4 issues apart -> 4 independent HMMA in flight per warp (latency cover).
// ---------------------------------------------------------------------------
#define SROW 12                        // uint32 per row
#define PLU (128*SROW)                 // uint32 per plane = 1536
#define STGU (4*PLU)                   // uint32 per stage = 6144 (24KB)
#define GSMB (4*STGU*4)                // bytes = 98304 (4 stages)

__device__ __forceinline__ void gemm3_tile(const bf16* __restrict__ Ah,
                                           const bf16* __restrict__ Al,
                                           const bf16* __restrict__ Bh,
                                           const bf16* __restrict__ Bl,
                                           float* __restrict__ C,
                                           int Ncol, int K) {
    extern __shared__ uint32_t smu[];
    const uint32_t sbase = smem_u32(smu);
    const int tid = threadIdx.x;
    const int warp = tid >> 5, lane = tid & 31;
    const int wm = (warp >> 2) * 64;      // 0 / 64
    const int wn = (warp & 3) * 32;       // 0..96
    const int r = lane >> 2, cf = lane & 3;

    const int row = tid >> 1, half = tid & 1;   // loader: 1 seg/plane/thread

    auto copy = [&](int kt, int slot) {
        uint32_t db = sbase + (uint32_t)(slot * STGU + row * SROW + half * 4) * 4u;
        size_t go = (size_t)row * K + (size_t)kt * 16 + half * 8;
        cp16(db,                 Ah + go);
        cp16(db + PLU * 4u,      Al + go);
        cp16(db + 2u * PLU * 4u, Bh + go);
        cp16(db + 3u * PLU * 4u, Bl + go);
    };

    // ldmatrix lane-address components
    const uint32_t a_row = (uint32_t)(wm + ((lane >> 3) & 1) * 8 + (lane & 7));
    const uint32_t a_kof = (uint32_t)((lane >> 4) * 4);
    const uint32_t b_row = (uint32_t)(wn + ((lane >> 4) & 1) * 8 + (lane & 7));
    const uint32_t b_kof = (uint32_t)(((lane >> 3) & 1) * 4);

    float acc[4][4][4] = {};

    auto compute = [&](int slot) {
        const uint32_t S = sbase + (uint32_t)(slot * STGU) * 4u;
        uint32_t bh[2][4], bl[2][4];      // [nt-pair][4 regs]
        #pragma unroll
        for (int p = 0; p < 2; p++) {
            uint32_t ad = S + 2u * PLU * 4u + ((b_row + p * 16) * SROW + b_kof) * 4u;
            ldsm4(bh[p], ad);
            ldsm4(bl[p], ad + PLU * 4u);
        }
        #pragma unroll
        for (int mt = 0; mt < 4; mt++) {
            uint32_t ah[4], al[4];
            uint32_t ad = S + ((a_row + mt * 16) * SROW + a_kof) * 4u;
            ldsm4(ah, ad);
            ldsm4(al, ad + PLU * 4u);
            // Term-grouped order: same-acc mmas are 4 apart (ILP=4)
            #pragma unroll
            for (int nt = 0; nt < 4; nt++)
                mma_bf16(acc[mt][nt], ah, &bh[nt >> 1][(nt & 1) * 2]);
            #pragma unroll
            for (int nt = 0; nt < 4; nt++)
                mma_bf16(acc[mt][nt], ah, &bl[nt >> 1][(nt & 1) * 2]);
            #pragma unroll
            for (int nt = 0; nt < 4; nt++)
                mma_bf16(acc[mt][nt], al, &bh[nt >> 1][(nt & 1) * 2]);
        }
    };

    const int NK = K / 16;
    copy(0, 0); CP_COMMIT();
    copy(1, 1); CP_COMMIT();
    copy(2, 2); CP_COMMIT();
    for (int kt = 0; kt < NK; kt++) {
        CP_WAIT2();                       // stage kt arrived (3 commits back)
        __syncthreads();
        if (kt + 3 < NK) copy(kt + 3, (kt + 3) & 3);
        CP_COMMIT();                      // uniform commit (possibly empty)
        compute(kt & 3);
    }

    // Epilogue: mma C-fragment layout, float2 stores
    #pragma unroll
    for (int mt = 0; mt < 4; mt++) {
        int rowc = wm + mt * 16 + r;
        #pragma unroll
        for (int nt = 0; nt < 4; nt++) {
            int col = wn + nt * 8 + cf * 2;
            float2 lo = {acc[mt][nt][0], acc[mt][nt][1]};
            float2 hi = {acc[mt][nt][2], acc[mt][nt][3]};
            *(float2*)(C + (size_t)rowc * Ncol + col) = lo;
            *(float2*)(C + (size_t)(rowc + 8) * Ncol + col) = hi;
        }
    }
}

// K/V/Q projections fused via blockIdx.z
__global__ void __launch_bounds__(256, 2) gemm_kvq() {
    const bf16 *Bh, *Bl;
    float* C;
    if (blockIdx.z == 0)      { Bh = d_wKh; Bl = d_wKl; C = d_K; }
    else if (blockIdx.z == 1) { Bh = d_wVh; Bl = d_wVl; C = d_V; }
    else                      { Bh = d_wQh; Bl = d_wQl; C = d_Q; }
    gemm3_tile(d_Xh + (size_t)blockIdx.y * 128 * 1024, d_Xl + (size_t)blockIdx.y * 128 * 1024,
               Bh + (size_t)blockIdx.x * 128 * 1024, Bl + (size_t)blockIdx.x * 128 * 1024,
               C + (size_t)blockIdx.y * 128 * 512 + blockIdx.x * 128,
               512, 1024);
}

// Output GEMM: out = Y * wO = Y * (wOT)^T
__global__ void __launch_bounds__(256, 2) gemm_out(float* __restrict__ out) {
    gemm3_tile(d_Yh + (size_t)blockIdx.y * 128 * 512, d_Yl + (size_t)blockIdx.y * 128 * 512,
               d_wOh + (size_t)blockIdx.x * 128 * 512, d_wOl + (size_t)blockIdx.x * 128 * 512,
               out + (size_t)blockIdx.y * 128 * 1024 + blockIdx.x * 128,
               1024, 512);
}

// ---------------------------------------------------------------------------
// One-shot weight split: wK/wV/wQ -> bf16 hi/lo planes (by blockIdx.y)
// ---------------------------------------------------------------------------
__global__ void __launch_bounds__(256) split_w(const float* __restrict__ wK,
                                               const float* __restrict__ wV,
                                               const float* __restrict__ wQ) {
    const float* src = (blockIdx.y == 0) ? wK : (blockIdx.y == 1) ? wV : wQ;
    bf16* dh = (blockIdx.y == 0) ? d_wKh : (blockIdx.y == 1) ? d_wVh : d_wQh;
    bf16* dl = (blockIdx.y == 0) ? d_wKl : (blockIdx.y == 1) ? d_wVl : d_wQl;
    int i = blockIdx.x * 256 + threadIdx.x;      // float4 index, 131072 total
    float4 v = *(const float4*)(src + (size_t)i * 4);
    bf16 h[4], l[4];
    split_bf(v.x, h[0], l[0]); split_bf(v.y, h[1], l[1]);
    split_bf(v.z, h[2], l[2]); split_bf(v.w, h[3], l[3]);
    *(bf162*)(dh + (size_t)i * 4)     = bf162{h[0], h[1]};
    *(bf162*)(dh + (size_t)i * 4 + 2) = bf162{h[2], h[3]};
    *(bf162*)(dl + (size_t)i * 4)     = bf162{l[0], l[1]};
    *(bf162*)(dl + (size_t)i * 4 + 2) = bf162{l[2], l[3]};
}

// wO (512 x 1024 row-major) -> transposed + split (1024 x 512) bf16 hi/lo
__global__ void transpose_wo(const float* __restrict__ wo) {
    __shared__ float t[32][33];
    int bx = blockIdx.x * 32;   // over N (1024)
    int by = blockIdx.y * 32;   // over K (512)
    int x = threadIdx.x, y = threadIdx.y;
    #pragma unroll
    for (int j = 0; j < 32; j += 8)
        t[y + j][x] = wo[(size_t)(by + y + j) * 1024 + bx + x];
    __syncthreads();
    #pragma unroll
    for (int j = 0; j < 32; j += 8) {
        float v = t[x][y + j];
        bf16 h, l;
        split_bf(v, h, l);
        d_wOh[(size_t)(bx + y + j) * 512 + by + x] = h;
        d_wOl[(size_t)(bx + y + j) * 512 + by + x] = l;
    }
}

// ---------------------------------------------------------------------------
// G projection + bias + sigmoid; also emits X hi/lo bf16 planes.
// ---------------------------------------------------------------------------
__global__ void __launch_bounds__(256) g_kernel(const float* __restrict__ X,
                                                const float* __restrict__ wG,
                                                const float* __restrict__ bG) {
    __shared__ float xs[8][1024];
    const int tid = threadIdx.x;
    const int token0 = blockIdx.x * 8;
    #pragma unroll
    for (int i = 0; i < 8; i++) {
        int idx = tid + i * 256;              // float4 index 0..2047
        int tok = idx >> 8, c4 = idx & 255;
        float4 v = *(const float4*)(X + (size_t)(token0 + tok) * DMc + c4 * 4);
        *(float4*)&xs[tok][c4 * 4] = v;
        bf16 h[4], l[4];
        split_bf(v.x, h[0], l[0]); split_bf(v.y, h[1], l[1]);
        split_bf(v.z, h[2], l[2]); split_bf(v.w, h[3], l[3]);
        size_t o = (size_t)(token0 + tok) * DMc + c4 * 4;
        *(bf162*)(d_Xh + o)     = bf162{h[0], h[1]};
        *(bf162*)(d_Xh + o + 2) = bf162{h[2], h[3]};
        *(bf162*)(d_Xl + o)     = bf162{l[0], l[1]};
        *(bf162*)(d_Xl + o + 2) = bf162{l[2], l[3]};
    }
    __syncthreads();

    const int w = tid >> 5, lane = tid & 31;
    float acc[4][8] = {};
    #pragma unroll 4
    for (int j = 0; j < 32; j++) {
        int k = j * 32 + lane;
        float wv[4];
        #pragma unroll
        for (int o = 0; o < 4; o++)
            wv[o] = wG[(size_t)(w * 4 + o) * DMc + k];
        #pragma unroll
        for (int tok = 0; tok < 8; tok++) {
            float xv = xs[tok][k];
            #pragma unroll
            for (int o = 0; o < 4; o++)
                acc[o][tok] += wv[o] * xv;
        }
    }
    #pragma unroll
    for (int o = 0; o < 4; o++) {
        float bias = bG[w * 4 + o];
        #pragma unroll
        for (int tok = 0; tok < 8; tok++) {
            float v = acc[o][tok];
            #pragma unroll
            for (int off = 16; off; off >>= 1)
                v += __shfl_xor_sync(0xffffffffu, v, off);
            if (lane == 0)
                d_Gsig[(size_t)(token0 + tok) * (Hh * Ee) + w * 4 + o] =
                    1.f / (1.f + expf(-(v + bias)));
        }
    }
}

// ---------------------------------------------------------------------------
// Gating: per (n,e,t) compute gated_K, gated_V (sum over heads), and A.
// ---------------------------------------------------------------------------
__global__ void __launch_bounds__(128) gated_kernel() {
    const int blk = blockIdx.x;
    const int t = blk % Tt;
    const int e = (blk / Tt) % Ee;
    const int n = blk / (Tt * Ee);
    const int token = n * Tt + t;
    __shared__ float g[Hh];
    const int tid = threadIdx.x;
    if (tid < Hh)
        g[tid] = d_Gsig[token * (Hh * Ee) + tid * Ee + e];
    __syncthreads();
    if (tid < 64) {
        float s = 0.f;
        #pragma unroll
        for (int h = 0; h < Hh; h++) s += g[h] * d_K[token * (Hh * DKc) + h * DKc + tid];
        d_gK[((n * Ee + e) * Tt + t) * DKc + tid] = s;
    } else {
        int dd = tid - 64;
        float s = 0.f;
        #pragma unroll
        for (int h = 0; h < Hh; h++) s += g[h] * d_V[token * (Hh * DVc) + h * DVc + dd];
        d_gV[((n * Ee + e) * Tt + t) * DVc + dd] = s;
    }
    if (tid == 0) {
        float sa = 0.f;
        #pragma unroll
        for (int h = 0; h < Hh; h++) sa += g[h];
        d_A[(n * Ee + e) * Tt + t] = 1.f - sa;
    }
}

// ---------------------------------------------------------------------------
// Scan: L-strided recurrence rec[t] = A[t]*rec[t-L] + gated[t].
// ---------------------------------------------------------------------------
__global__ void __launch_bounds__(128) scan_kernel(const float* __restrict__ initK,
                                                   const float* __restrict__ initV) {
    const int b = blockIdx.x;             // Nn*Ee*Ll = 256 blocks
    const int l = b % Ll;
    const int e = (b / Ll) % Ee;
    const int n = b / (Ll * Ee);
    const int d = threadIdx.x;
    const bool isK = d < 64;
    const int dd = isK ? d : d - 64;
    const float* init = isK ? initK : initV;
    const float* gsrc = isK ? d_gK : d_gV;
    float* rec = isK ? d_recK : d_recV;
    const int ne = n * Ee + e;
    float y = init[(e * Ll + l) * 64 + dd];
    rec[(ne * REC_T + l) * 64 + dd] = y;
    const float* Arow = d_A + ne * Tt;
    const float* grow = gsrc + ne * Tt * 64;
    float* rrow = rec + (ne * REC_T + Ll) * 64;
    #pragma unroll 4
    for (int m = 0; m < M_CH; m++) {
        int t = m * Ll + l;
        y = Arow[t] * y + grow[t * 64 + dd];
        rrow[t * 64 + dd] = y;
    }
}

// ---------------------------------------------------------------------------
// Attention: one block per token (n,t); all H=8 heads share the same
// 128-slot key/value window (E=4 experts x L=32 positions).
// Epilogue writes Y directly as bf16 hi/lo planes for the output GEMM.
// ---------------------------------------------------------------------------
__global__ void __launch_bounds__(256) attn_kernel() {
    extern __shared__ float smem[];
    float* qs = smem;                      // 512
    float* Ks = qs + Hh * DKc;             // 128*65 (padded rows)
    float* Vs = Ks + 128 * 65;             // 128*65
    float* sc = Vs + 128 * 65;             // 8*128
    const int token = blockIdx.x;
    const int n = token / Tt, t = token % Tt;
    const int tid = threadIdx.x;

    qs[tid]       = d_Q[token * 512 + tid];
    qs[tid + 256] = d_Q[token * 512 + tid + 256];

    for (int i = tid; i < 128 * 64; i += 256) {
        int j = i >> 6, dd = i & 63;
        int e = j >> 5;
        int pos = t + (j & 31) + 1;                 // <= 2079 < REC_T
        int off = ((n * Ee + e) * REC_T + pos) * 64 + dd;
        Ks[j * 65 + dd] = d_recK[off];
        Vs[j * 65 + dd] = d_recV[off];
    }
    __syncthreads();

    // scores: 8 heads x 128 slots = 1024 tasks
    #pragma unroll
    for (int r = 0; r < 4; r++) {
        int task = tid + r * 256;
        int h = task >> 7, j = task & 127;
        const float* qrow = qs + h * 64;
        const float* krow = Ks + j * 65;
        float s = 0.f;
        #pragma unroll
        for (int d = 0; d < 64; d++) s += qrow[d] * krow[d];
        sc[h * 128 + j] = s * 0.125f;               // 1/sqrt(64)
    }
    __syncthreads();

    // softmax over 128 slots: warp w handles head h=w
    {
        int h = tid >> 5, lane = tid & 31;
        float v0 = sc[h * 128 + lane];
        float v1 = sc[h * 128 + lane + 32];
        float v2 = sc[h * 128 + lane + 64];
        float v3 = sc[h * 128 + lane + 96];
        float mx = fmaxf(fmaxf(v0, v1), fmaxf(v2, v3));
        #pragma unroll
        for (int o = 16; o; o >>= 1) mx = fmaxf(mx, __shfl_xor_sync(0xffffffffu, mx, o));
        float e0 = expf(v0 - mx), e1 = expf(v1 - mx);
        float e2 = expf(v2 - mx), e3 = expf(v3 - mx);
        float ssum = e0 + e1 + e2 + e3;
        #pragma unroll
        for (int o = 16; o; o >>= 1) ssum += __shfl_xor_sync(0xffffffffu, ssum, o);
        float inv = 1.f / ssum;
        sc[h * 128 + lane]      = e0 * inv;
        sc[h * 128 + lane + 32] = e1 * inv;
        sc[h * 128 + lane + 64] = e2 * inv;
        sc[h * 128 + lane + 96] = e3 * inv;
    }
    __syncthreads();

    // output: 8 heads x 64 dims = 512 outputs, split to bf16 hi/lo
    #pragma unroll
    for (int r = 0; r < 2; r++) {
        int o = tid + r * 256;
        int h = o >> 6, dd = o & 63;
        const float* arow = sc + h * 128;
        float acc = 0.f;
        #pragma unroll 4
        for (int j = 0; j < 128; j++) acc += arow[j] * Vs[j * 65 + dd];
        bf16 hp, lp;
        split_bf(acc, hp, lp);
        d_Yh[token * 512 + o] = hp;
        d_Yl[token * 512 + o] = lp;
    }
}

// ---------------------------------------------------------------------------
extern "C" void kernel_launch(void* const* d_in, const int* in_sizes, int n_in,
                              void* d_out, int out_size) {
    const float* X  = (const float*)d_in[0];
    const float* wG = (const float*)d_in[1];
    const float* bG = (const float*)d_in[2];
    const float* wK = (const float*)d_in[3];
    const float* wV = (const float*)d_in[4];
    const float* wQ = (const float*)d_in[5];
    const float* wO = (const float*)d_in[6];
    const float* iK = (const float*)d_in[7];
    const float* iV = (const float*)d_in[8];
    float* out = (float*)d_out;

    cudaFuncSetAttribute(gemm_kvq, cudaFuncAttributeMaxDynamicSharedMemorySize, GSMB);
    cudaFuncSetAttribute(gemm_out, cudaFuncAttributeMaxDynamicSharedMemorySize, GSMB);

    // One-shot operand preparation (splits + transpose)
    split_w<<<dim3(512, 3), 256>>>(wK, wV, wQ);
    transpose_wo<<<dim3(32, 16), dim3(32, 8)>>>(wO);
    g_kernel<<<NT / 8, 256>>>(X, wG, bG);     // also emits d_Xh / d_Xl

    // K/V/Q projections on pre-split bf16 planes, fused on grid.z
    gemm_kvq<<<dim3(4, 32, 3), 256, GSMB>>>();

    gated_kernel<<<Nn * Ee * Tt, 128>>>();
    scan_kernel<<<Nn * Ee * Ll, 128>>>(iK, iV);

    static const size_t attn_smem = (512 + 2 * 128 * 65 + 8 * 128) * sizeof(float);
    cudaFuncSetAttribute(attn_kernel, cudaFuncAttributeMaxDynamicSharedMemorySize,
                         (int)attn_smem);
    attn_kernel<<<NT, 256, attn_smem>>>();

    // Output: out = Y * wO = Y * (wOT)^T
    gemm_out<<<dim3(8, 32), 256, GSMB>>>(out);
}